// round 15
// baseline (speedup 1.0000x reference)
#include <cuda_runtime.h>

#define BB 2
#define SS 1024
#define DD 128
#define NCHUNK 16          // k chunks of 64

// Scratch (device globals; allocation-free per harness rules)
__device__ float g_Q[BB*SS*DD];
__device__ float g_K[BB*SS*DD];
__device__ float g_V[BB*SS*DD];
__device__ float g_sQp[2][BB*SS];             // per-e-half row-sum partials of Q
__device__ float g_sKp[2][BB*SS];             // per-e-half row-sum partials of K
__device__ float g_part[NCHUNK][BB*SS*DD];    // split-K partials ((P-1) weighted)
__device__ float g_rsum[NCHUNK][BB*SS];       // split-K partial row sums of exp
__device__ float g_vseg16[BB*64*DD];          // per-16-row segment sums of V (from qkv)
__device__ float g_vtot[BB*DD];               // total V row-sum per batch (from fused tail)

// ---------------------------------------------------------------------------
// K1: Q/K/V projection, fine-grained: 16 rows x 64 e per block, d=128
// resident (single sync).  grid (128 row-tiles, 2 e-halves, 3 mats) = 768
// blocks, block 256 (ty=row 0..15, tx=e-group 0..15).  smem 42.2KB -> 5/SM.
// ---------------------------------------------------------------------------
__global__ __launch_bounds__(256) void qkv_kernel(
    const float* __restrict__ x,
    const float* __restrict__ Wq, const float* __restrict__ bq,
    const float* __restrict__ Wk, const float* __restrict__ bk,
    const float* __restrict__ Wv, const float* __restrict__ bv)
{
    __shared__ float xs[16*132];
    __shared__ float ws[64*132];
    const int t  = threadIdx.x;
    const int tx = t & 15;          // e = ebase + tx + 16*j, j<4
    const int ty = t >> 4;          // row ty (16 rows)
    const int ehalf = blockIdx.y;
    const int mat = blockIdx.z;
    const int rowbase = blockIdx.x * 16;      // global row (spans batches)
    const int ebase = ehalf * 64;

    const float* W    = (mat == 0) ? Wq : (mat == 1) ? Wk : Wv;
    const float* bias = (mat == 0) ? bq : (mat == 1) ? bk : bv;

    // W half [64 e][128 d]: 64*32 float4 / 256 thr = 8 each
    #pragma unroll
    for (int i = 0; i < 8; i++) {
        int lin = t + i*256;
        int e = lin >> 5, c4 = lin & 31;
        *(float4*)(ws + e*132 + c4*4) = *(const float4*)(W + (ebase + e)*DD + c4*4);
    }
    // x tile [16 rows][128 d]: 16*32 float4 / 256 = 2 each
    #pragma unroll
    for (int i = 0; i < 2; i++) {
        int lin = t + i*256;
        int r = lin >> 5, c4 = lin & 31;
        *(float4*)(xs + r*132 + c4*4) = *(const float4*)(x + (rowbase + r)*DD + c4*4);
    }
    __syncthreads();

    float acc[4] = {0.f, 0.f, 0.f, 0.f};
    #pragma unroll 8
    for (int d4 = 0; d4 < 32; d4++) {
        float4 xv = *(const float4*)(xs + ty*132 + d4*4);
        #pragma unroll
        for (int j = 0; j < 4; j++) {
            float4 w = *(const float4*)(ws + (tx + 16*j)*132 + d4*4);
            acc[j] += xv.x*w.x; acc[j] += xv.y*w.y;
            acc[j] += xv.z*w.z; acc[j] += xv.w*w.w;
        }
    }

    float* out = (mat == 0) ? g_Q : (mat == 1) ? g_K : g_V;
    int r = rowbase + ty;
    float rsum = 0.f;
    float vvals[4];
    #pragma unroll
    for (int j = 0; j < 4; j++) {
        int e = ebase + tx + 16*j;
        float v = acc[j] + bias[e];
        if (mat < 2) v = 1.f / (1.f + __expf(-v));
        rsum += v;
        vvals[j] = v;
        out[r*DD + e] = v;
    }

    if (mat < 2) {
        #pragma unroll
        for (int o = 1; o < 16; o <<= 1)
            rsum += __shfl_xor_sync(0xffffffffu, rsum, o);
        if (tx == 0) {
            float* dst = (mat == 0) ? g_sQp[ehalf] : g_sKp[ehalf];
            dst[r] = rsum;
        }
    } else {
        // V column sums over this block's 16 rows for its 64 columns
        __syncthreads();                  // xs reads complete
        float* vsum = xs;                 // reuse: 16 x 64 (stride 132 ok)
        #pragma unroll
        for (int j = 0; j < 4; j++)
            vsum[ty*132 + tx + 16*j] = vvals[j];
        __syncthreads();
        if (t < 64) {
            float ssum = 0.f;
            #pragma unroll
            for (int rr = 0; rr < 16; rr++) ssum += vsum[rr*132 + t];
            g_vseg16[blockIdx.x * DD + ebase + t] = ssum;
        }
    }
}

// ---------------------------------------------------------------------------
// Triangular chunk base: B(qi) = qi + floor((qi-1)^2/4), B(0) = 0.
// ---------------------------------------------------------------------------
__device__ __forceinline__ int tri_base(int qi)
{
    return (qi == 0) ? 0 : qi + ((qi - 1)*(qi - 1)) / 4;
}

// ---------------------------------------------------------------------------
// Fused flash-style kernel (R14-exact).  Tail block (x==512, y==0) computes
// g_vtot from the 64 16-row segments per batch.  grid (513, B), block 256.
// ---------------------------------------------------------------------------
#define QS_OFF 0
#define KS_OFF (32*132)
#define VS_OFF (2*32*132)
#define SS_OFF (3*32*132)
#define FUSED_SMEM_BYTES ((3*32*132 + 32*36) * 4)

__global__ __launch_bounds__(256) void fused_kernel(const int* __restrict__ maskflag)
{
    const int causal = (maskflag[0] != 0);
    const int n = blockIdx.x;
    const int b = blockIdx.y;

    if (n == 512) {                       // vtot tail block
        if (b == 0) {
            int bb = threadIdx.x >> 7, d = threadIdx.x & 127;
            float a = 0.f;
            #pragma unroll 8
            for (int s2 = 0; s2 < 64; s2++)
                a += g_vseg16[(bb*64 + s2)*DD + d];
            g_vtot[bb*DD + d] = a;
        }
        return;
    }

    int qi, kc;
    if (causal) {
        if (n >= 272) return;
        qi = (int)(2.f * sqrtf((float)n + 1.f)) - 2;
        if (qi < 0) qi = 0;
        if (qi > 31) qi = 31;
        while (qi < 31 && tri_base(qi + 1) <= n) qi++;
        while (qi > 0  && tri_base(qi) > n)      qi--;
        kc = n - tri_base(qi);
    } else {
        qi = n >> 4;
        kc = n & 15;
    }
    const int qt = qi * 32;

    extern __shared__ float smem[];
    float* qs = smem + QS_OFF;
    float* ks = smem + KS_OFF;
    float* vs = smem + VS_OFF;
    float* ss = smem + SS_OFF;

    const int t  = threadIdx.x;
    const int tx = t & 15;         // score: k = k0 + tx, +16
    const int ty = t >> 4;         // score: q = qt + ty, +16
    const int tx2 = t & 31;        // pv: d = tx2*4
    const int ty2 = t >> 5;        // pv: q = ty2 + 8i

    const float* Qb = g_Q + b*SS*DD;
    const float* Kb = g_K + b*SS*DD;
    const float* Vb = g_V + b*SS*DD;

    #pragma unroll
    for (int i = 0; i < 4; i++) {
        int lin = t + i*256;
        int r = lin >> 5, c = (lin & 31) * 4;
        *(float4*)(qs + r*132 + c) = *(const float4*)(Qb + (qt + r)*DD + c);
    }
    const float sQ0 = g_sQp[0][b*SS + qt + ty]      + g_sQp[1][b*SS + qt + ty];
    const float sQ1 = g_sQp[0][b*SS + qt + ty + 16] + g_sQp[1][b*SS + qt + ty + 16];

    float4 oacc[4];
    #pragma unroll
    for (int i = 0; i < 4; i++) oacc[i] = make_float4(0.f,0.f,0.f,0.f);
    float rs0 = 0.f, rs1 = 0.f;

    #pragma unroll
    for (int s = 0; s < 2; s++) {
        const int k0 = kc*64 + s*32;

        __syncthreads();
        // async V tile prefetch (lands before PV; overlapped with score)
        #pragma unroll
        for (int i = 0; i < 4; i++) {
            int lin = t + i*256;
            int r = lin >> 5, c = (lin & 31) * 4;
            unsigned dst = (unsigned)__cvta_generic_to_shared(vs + r*132 + c);
            const float* src = Vb + (k0 + r)*DD + c;
            asm volatile("cp.async.cg.shared.global [%0], [%1], 16;\n"
                         :: "r"(dst), "l"(src) : "memory");
        }
        asm volatile("cp.async.commit_group;\n" ::: "memory");
        // K tile (regular ld/st; covered by the next barrier)
        #pragma unroll
        for (int i = 0; i < 4; i++) {
            int lin = t + i*256;
            int r = lin >> 5, c = (lin & 31) * 4;
            *(float4*)(ks + r*132 + c) = *(const float4*)(Kb + (k0 + r)*DD + c);
        }
        __syncthreads();

        // --- score: A = sum_d |q - k| ---
        float a00 = 0.f, a01 = 0.f, a10 = 0.f, a11 = 0.f;
        #pragma unroll 8
        for (int dq = 0; dq < 32; dq++) {
            float4 q0 = *(const float4*)(qs + ty*132 + dq*4);
            float4 q1 = *(const float4*)(qs + (ty+16)*132 + dq*4);
            float4 k0v = *(const float4*)(ks + tx*132 + dq*4);
            float4 k1v = *(const float4*)(ks + (tx+16)*132 + dq*4);
            a00 += fabsf(q0.x-k0v.x); a00 += fabsf(q0.y-k0v.y);
            a00 += fabsf(q0.z-k0v.z); a00 += fabsf(q0.w-k0v.w);
            a01 += fabsf(q0.x-k1v.x); a01 += fabsf(q0.y-k1v.y);
            a01 += fabsf(q0.z-k1v.z); a01 += fabsf(q0.w-k1v.w);
            a10 += fabsf(q1.x-k0v.x); a10 += fabsf(q1.y-k0v.y);
            a10 += fabsf(q1.z-k0v.z); a10 += fabsf(q1.w-k0v.w);
            a11 += fabsf(q1.x-k1v.x); a11 += fabsf(q1.y-k1v.y);
            a11 += fabsf(q1.z-k1v.z); a11 += fabsf(q1.w-k1v.w);
        }
        const float sK0 = g_sKp[0][b*SS + k0 + tx]      + g_sKp[1][b*SS + k0 + tx];
        const float sK1 = g_sKp[0][b*SS + k0 + tx + 16] + g_sKp[1][b*SS + k0 + tx + 16];

        float e00 = __expf(10.f - (sQ0 - sK0 + a00)*(10.f/256.f));
        float e01 = __expf(10.f - (sQ0 - sK1 + a01)*(10.f/256.f));
        float e10 = __expf(10.f - (sQ1 - sK0 + a10)*(10.f/256.f));
        float e11 = __expf(10.f - (sQ1 - sK1 + a11)*(10.f/256.f));
        if (causal) {
            int q0g = qt + ty, q1g = qt + ty + 16;
            int k0g = k0 + tx, k1g = k0 + tx + 16;
            if (k0g > q0g) e00 = 0.f;
            if (k1g > q0g) e01 = 0.f;
            if (k0g > q1g) e10 = 0.f;
            if (k1g > q1g) e11 = 0.f;
        }
        float l0 = e00 + e01, l1 = e10 + e11;
        #pragma unroll
        for (int o = 1; o < 16; o <<= 1) {
            l0 += __shfl_xor_sync(0xffffffffu, l0, o);
            l1 += __shfl_xor_sync(0xffffffffu, l1, o);
        }
        if (tx == 0) { rs0 += l0; rs1 += l1; }

        ss[ty*36 + tx]           = (e00 == 0.f) ? 0.f : e00 - 1.f;
        ss[ty*36 + tx + 16]      = (e01 == 0.f) ? 0.f : e01 - 1.f;
        ss[(ty+16)*36 + tx]      = (e10 == 0.f) ? 0.f : e10 - 1.f;
        ss[(ty+16)*36 + tx + 16] = (e11 == 0.f) ? 0.f : e11 - 1.f;

        asm volatile("cp.async.wait_group 0;\n" ::: "memory");
        __syncthreads();

        // --- PV accumulate (V from smem) ---
        #pragma unroll 2
        for (int kq = 0; kq < 8; kq++) {
            float4 p0 = *(const float4*)(ss + (ty2    )*36 + kq*4);
            float4 p1 = *(const float4*)(ss + (ty2+ 8)*36 + kq*4);
            float4 p2 = *(const float4*)(ss + (ty2+16)*36 + kq*4);
            float4 p3 = *(const float4*)(ss + (ty2+24)*36 + kq*4);
            #pragma unroll
            for (int c = 0; c < 4; c++) {
                float4 v = *(const float4*)(vs + (kq*4 + c)*132 + tx2*4);
                float pf0 = (&p0.x)[c], pf1 = (&p1.x)[c];
                float pf2 = (&p2.x)[c], pf3 = (&p3.x)[c];
                oacc[0].x += pf0*v.x; oacc[0].y += pf0*v.y; oacc[0].z += pf0*v.z; oacc[0].w += pf0*v.w;
                oacc[1].x += pf1*v.x; oacc[1].y += pf1*v.y; oacc[1].z += pf1*v.z; oacc[1].w += pf1*v.w;
                oacc[2].x += pf2*v.x; oacc[2].y += pf2*v.y; oacc[2].z += pf2*v.z; oacc[2].w += pf2*v.w;
                oacc[3].x += pf3*v.x; oacc[3].y += pf3*v.y; oacc[3].z += pf3*v.z; oacc[3].w += pf3*v.w;
            }
        }
    }

    float* dst = g_part[kc] + ((b << 10) + qt)*DD;
    #pragma unroll
    for (int i = 0; i < 4; i++)
        *(float4*)(dst + (ty2 + 8*i)*DD + tx2*4) = oacc[i];
    if (tx == 0) {
        g_rsum[kc][(b << 10) + qt + ty]      = rs0;
        g_rsum[kc][(b << 10) + qt + ty + 16] = rs1;
    }
}

// ---------------------------------------------------------------------------
// Reduce: out = (sum of active chunk partials + Vtot) * rinv.
// ---------------------------------------------------------------------------
__global__ __launch_bounds__(128) void out_reduce_kernel(float* __restrict__ out,
                                                          const int* __restrict__ maskflag)
{
    const int causal = (maskflag[0] != 0);
    int idx4 = blockIdx.x * 128 + threadIdx.x;
    int base = idx4 * 4;
    int row  = base >> 7;              // b*SS + q  (shared by all 32 lanes)
    int q    = row & (SS-1);
    int b    = row >> 10;
    int doff = base & 127;
    int lane = threadIdx.x & 31;

    int nc = causal ? ((q >> 6) + 1) : NCHUNK;

    float rp = (lane < nc) ? g_rsum[lane][row] : 0.f;
    #pragma unroll
    for (int o = 16; o > 0; o >>= 1) rp += __shfl_xor_sync(0xffffffffu, rp, o);
    float denom = rp + (causal ? (float)(SS - 1 - q) : 0.f);
    float rv = 1.f / denom;

    float4 s = *(const float4*)(g_vtot + (b << 7) + doff);
    #pragma unroll 4
    for (int j = 0; j < nc; j++) {
        float4 p = *(const float4*)(&g_part[j][base]);
        s.x += p.x; s.y += p.y; s.z += p.z; s.w += p.w;
    }
    s.x *= rv; s.y *= rv; s.z *= rv; s.w *= rv;
    *(float4*)(out + base) = s;
}

// ---------------------------------------------------------------------------
extern "C" void kernel_launch(void* const* d_in, const int* in_sizes, int n_in,
                              void* d_out, int out_size)
{
    const float* x  = (const float*)d_in[0];
    const float* Wq = (const float*)d_in[1];
    const float* bq = (const float*)d_in[2];
    const float* Wk = (const float*)d_in[3];
    const float* bk = (const float*)d_in[4];
    const float* Wv = (const float*)d_in[5];
    const float* bv = (const float*)d_in[6];
    const int*  msk = (const int*)d_in[7];
    float* out = (float*)d_out;

    cudaFuncSetAttribute(fused_kernel,
                         cudaFuncAttributeMaxDynamicSharedMemorySize,
                         FUSED_SMEM_BYTES);

    qkv_kernel    <<<dim3(BB*SS/16, 2, 3), 256>>>(x, Wq, bq, Wk, bk, Wv, bv);
    fused_kernel  <<<dim3(513, BB), 256, FUSED_SMEM_BYTES>>>(msk);
    out_reduce_kernel<<<BB*SS*DD/512, 128>>>(out, msk);
}

// round 16
// speedup vs baseline: 1.1312x; 1.1312x over previous
#include <cuda_runtime.h>

#define BB 2
#define SS 1024
#define DD 128
#define NCHUNK 16          // k chunks of 64

// Scratch (device globals; allocation-free per harness rules)
__device__ float g_Q[BB*SS*DD];
__device__ float g_K[BB*SS*DD];
__device__ float g_V[BB*SS*DD];
__device__ float g_sQp[2][BB*SS];             // per-e-half row-sum partials of Q
__device__ float g_sKp[2][BB*SS];             // per-e-half row-sum partials of K
__device__ float g_part[NCHUNK][BB*SS*DD];    // split-K partials ((P-1) weighted)
__device__ float g_rsum[NCHUNK][BB*SS];       // split-K partial row sums of exp
__device__ float g_vseg32[BB*32*DD];          // per-32-row segment sums of V (from qkv)
__device__ float g_vtot[BB*DD];               // total V row-sum per batch (from fused tail)

// ---------------------------------------------------------------------------
// K1: Q/K/V projection (R14 shape: 32 rows x 64 e, acc[2][4]) with BOTH W
// d-chunks prefetched via cp.async at kernel entry — chunk1's load latency
// hides under chunk0's compute.  x tile full-d resident (conflict-free).
// grid (64, 2, 3) = 384 blocks (single wave), block 256, dyn smem 50KB.
// ---------------------------------------------------------------------------
#define QKV_SMEM_BYTES (32*128*4 + 2*64*68*4)   // xs 16KB + ws[2] 34KB = 50KB

__global__ __launch_bounds__(256) void qkv_kernel(
    const float* __restrict__ x,
    const float* __restrict__ Wq, const float* __restrict__ bq,
    const float* __restrict__ Wk, const float* __restrict__ bk,
    const float* __restrict__ Wv, const float* __restrict__ bv)
{
    extern __shared__ float qsm[];
    float* xs  = qsm;                 // [32][128], stride 128
    float* ws0 = qsm + 32*128;        // [64][68]
    float* ws1 = ws0 + 64*68;         // [64][68]

    const int t  = threadIdx.x;
    const int tx = t & 15;            // e = ebase + tx + 16*j, j<4
    const int ty = t >> 4;            // rows ty, ty+16
    const int ehalf = blockIdx.y;
    const int mat = blockIdx.z;
    const int rowbase = blockIdx.x * 32;
    const int ebase = ehalf * 64;

    const float* W    = (mat == 0) ? Wq : (mat == 1) ? Wk : Wv;
    const float* bias = (mat == 0) ? bq : (mat == 1) ? bk : bv;

    // prefetch BOTH W chunks ([64 e][64 d] each) via cp.async
    {
        float* wdst[2] = {ws0, ws1};
        #pragma unroll
        for (int c = 0; c < 2; c++) {
            #pragma unroll
            for (int i = 0; i < 4; i++) {
                int lin = t + i*256;
                int e = lin >> 4, c4 = lin & 15;
                unsigned dst = (unsigned)__cvta_generic_to_shared(wdst[c] + e*68 + c4*4);
                const float* src = W + (ebase + e)*DD + c*64 + c4*4;
                asm volatile("cp.async.cg.shared.global [%0], [%1], 16;\n"
                             :: "r"(dst), "l"(src) : "memory");
            }
            asm volatile("cp.async.commit_group;\n" ::: "memory");
        }
    }
    // x tile [32 rows][128 d] (regular float4 loads; row-per-warp = conflict-free)
    #pragma unroll
    for (int i = 0; i < 4; i++) {
        int lin = t + i*256;
        int r = lin >> 5, c = (lin & 31) * 4;
        *(float4*)(xs + r*128 + c) = *(const float4*)(x + (rowbase + r)*DD + c);
    }

    float acc[2][4];
    #pragma unroll
    for (int i = 0; i < 2; i++)
        #pragma unroll
        for (int j = 0; j < 4; j++) acc[i][j] = 0.f;

    // chunk 0
    asm volatile("cp.async.wait_group 1;\n" ::: "memory");
    __syncthreads();
    #pragma unroll
    for (int d4 = 0; d4 < 16; d4++) {
        float4 x0 = *(const float4*)(xs + ty*128 + d4*4);
        float4 x1 = *(const float4*)(xs + (ty+16)*128 + d4*4);
        #pragma unroll
        for (int j = 0; j < 4; j++) {
            float4 w = *(const float4*)(ws0 + (tx + 16*j)*68 + d4*4);
            acc[0][j] += x0.x*w.x; acc[0][j] += x0.y*w.y;
            acc[0][j] += x0.z*w.z; acc[0][j] += x0.w*w.w;
            acc[1][j] += x1.x*w.x; acc[1][j] += x1.y*w.y;
            acc[1][j] += x1.z*w.z; acc[1][j] += x1.w*w.w;
        }
    }
    // chunk 1 (load overlapped with chunk-0 compute)
    asm volatile("cp.async.wait_group 0;\n" ::: "memory");
    __syncthreads();
    #pragma unroll
    for (int d4 = 0; d4 < 16; d4++) {
        float4 x0 = *(const float4*)(xs + ty*128 + 64 + d4*4);
        float4 x1 = *(const float4*)(xs + (ty+16)*128 + 64 + d4*4);
        #pragma unroll
        for (int j = 0; j < 4; j++) {
            float4 w = *(const float4*)(ws1 + (tx + 16*j)*68 + d4*4);
            acc[0][j] += x0.x*w.x; acc[0][j] += x0.y*w.y;
            acc[0][j] += x0.z*w.z; acc[0][j] += x0.w*w.w;
            acc[1][j] += x1.x*w.x; acc[1][j] += x1.y*w.y;
            acc[1][j] += x1.z*w.z; acc[1][j] += x1.w*w.w;
        }
    }

    float* out = (mat == 0) ? g_Q : (mat == 1) ? g_K : g_V;
    float rsum[2] = {0.f, 0.f};
    float pairsum[4] = {0.f, 0.f, 0.f, 0.f};

    #pragma unroll
    for (int i = 0; i < 2; i++) {
        int r = rowbase + ty + 16*i;
        #pragma unroll
        for (int j = 0; j < 4; j++) {
            int e = ebase + tx + 16*j;
            float v = acc[i][j] + bias[e];
            if (mat < 2) v = 1.f / (1.f + __expf(-v));
            rsum[i] += v;
            pairsum[j] += v;
            out[r*DD + e] = v;
        }
    }
    if (mat < 2) {
        #pragma unroll
        for (int o = 1; o < 16; o <<= 1) {
            rsum[0] += __shfl_xor_sync(0xffffffffu, rsum[0], o);
            rsum[1] += __shfl_xor_sync(0xffffffffu, rsum[1], o);
        }
        if (tx == 0) {
            float* dst = (mat == 0) ? g_sQp[ehalf] : g_sKp[ehalf];
            dst[rowbase + ty]      = rsum[0];
            dst[rowbase + ty + 16] = rsum[1];
        }
    } else {
        // V column sums (32 rows) for this block's 64 columns
        __syncthreads();                   // all ws/xs reads complete
        float* vsum = ws0;                 // reuse: 16 x 64, stride 68
        #pragma unroll
        for (int j = 0; j < 4; j++)
            vsum[ty*68 + tx + 16*j] = pairsum[j];
        __syncthreads();
        if (t < 64) {
            float ssum = 0.f;
            #pragma unroll
            for (int r = 0; r < 16; r++) ssum += vsum[r*68 + t];
            g_vseg32[blockIdx.x * DD + ebase + t] = ssum;
        }
    }
}

// ---------------------------------------------------------------------------
// Triangular chunk base: B(qi) = qi + floor((qi-1)^2/4), B(0) = 0.
// ---------------------------------------------------------------------------
__device__ __forceinline__ int tri_base(int qi)
{
    return (qi == 0) ? 0 : qi + ((qi - 1)*(qi - 1)) / 4;
}

// ---------------------------------------------------------------------------
// Fused flash-style kernel (R14-exact).  Tail block (x==512, y==0) computes
// g_vtot from the 32 32-row segments per batch.  grid (513, B), block 256.
// ---------------------------------------------------------------------------
#define QS_OFF 0
#define KS_OFF (32*132)
#define VS_OFF (2*32*132)
#define SS_OFF (3*32*132)
#define FUSED_SMEM_BYTES ((3*32*132 + 32*36) * 4)

__global__ __launch_bounds__(256) void fused_kernel(const int* __restrict__ maskflag)
{
    const int causal = (maskflag[0] != 0);
    const int n = blockIdx.x;
    const int b = blockIdx.y;

    if (n == 512) {                       // vtot tail block
        if (b == 0) {
            int bb = threadIdx.x >> 7, d = threadIdx.x & 127;
            float a = 0.f;
            #pragma unroll 8
            for (int s2 = 0; s2 < 32; s2++)
                a += g_vseg32[(bb*32 + s2)*DD + d];
            g_vtot[bb*DD + d] = a;
        }
        return;
    }

    int qi, kc;
    if (causal) {
        if (n >= 272) return;
        qi = (int)(2.f * sqrtf((float)n + 1.f)) - 2;
        if (qi < 0) qi = 0;
        if (qi > 31) qi = 31;
        while (qi < 31 && tri_base(qi + 1) <= n) qi++;
        while (qi > 0  && tri_base(qi) > n)      qi--;
        kc = n - tri_base(qi);
    } else {
        qi = n >> 4;
        kc = n & 15;
    }
    const int qt = qi * 32;

    extern __shared__ float smem[];
    float* qs = smem + QS_OFF;
    float* ks = smem + KS_OFF;
    float* vs = smem + VS_OFF;
    float* ss = smem + SS_OFF;

    const int t  = threadIdx.x;
    const int tx = t & 15;         // score: k = k0 + tx, +16
    const int ty = t >> 4;         // score: q = qt + ty, +16
    const int tx2 = t & 31;        // pv: d = tx2*4
    const int ty2 = t >> 5;        // pv: q = ty2 + 8i

    const float* Qb = g_Q + b*SS*DD;
    const float* Kb = g_K + b*SS*DD;
    const float* Vb = g_V + b*SS*DD;

    #pragma unroll
    for (int i = 0; i < 4; i++) {
        int lin = t + i*256;
        int r = lin >> 5, c = (lin & 31) * 4;
        *(float4*)(qs + r*132 + c) = *(const float4*)(Qb + (qt + r)*DD + c);
    }
    const float sQ0 = g_sQp[0][b*SS + qt + ty]      + g_sQp[1][b*SS + qt + ty];
    const float sQ1 = g_sQp[0][b*SS + qt + ty + 16] + g_sQp[1][b*SS + qt + ty + 16];

    float4 oacc[4];
    #pragma unroll
    for (int i = 0; i < 4; i++) oacc[i] = make_float4(0.f,0.f,0.f,0.f);
    float rs0 = 0.f, rs1 = 0.f;

    #pragma unroll
    for (int s = 0; s < 2; s++) {
        const int k0 = kc*64 + s*32;

        __syncthreads();
        // async V tile prefetch (lands before PV; overlapped with score)
        #pragma unroll
        for (int i = 0; i < 4; i++) {
            int lin = t + i*256;
            int r = lin >> 5, c = (lin & 31) * 4;
            unsigned dst = (unsigned)__cvta_generic_to_shared(vs + r*132 + c);
            const float* src = Vb + (k0 + r)*DD + c;
            asm volatile("cp.async.cg.shared.global [%0], [%1], 16;\n"
                         :: "r"(dst), "l"(src) : "memory");
        }
        asm volatile("cp.async.commit_group;\n" ::: "memory");
        // K tile (regular ld/st; covered by the next barrier)
        #pragma unroll
        for (int i = 0; i < 4; i++) {
            int lin = t + i*256;
            int r = lin >> 5, c = (lin & 31) * 4;
            *(float4*)(ks + r*132 + c) = *(const float4*)(Kb + (k0 + r)*DD + c);
        }
        __syncthreads();

        // --- score: A = sum_d |q - k| ---
        float a00 = 0.f, a01 = 0.f, a10 = 0.f, a11 = 0.f;
        #pragma unroll 8
        for (int dq = 0; dq < 32; dq++) {
            float4 q0 = *(const float4*)(qs + ty*132 + dq*4);
            float4 q1 = *(const float4*)(qs + (ty+16)*132 + dq*4);
            float4 k0v = *(const float4*)(ks + tx*132 + dq*4);
            float4 k1v = *(const float4*)(ks + (tx+16)*132 + dq*4);
            a00 += fabsf(q0.x-k0v.x); a00 += fabsf(q0.y-k0v.y);
            a00 += fabsf(q0.z-k0v.z); a00 += fabsf(q0.w-k0v.w);
            a01 += fabsf(q0.x-k1v.x); a01 += fabsf(q0.y-k1v.y);
            a01 += fabsf(q0.z-k1v.z); a01 += fabsf(q0.w-k1v.w);
            a10 += fabsf(q1.x-k0v.x); a10 += fabsf(q1.y-k0v.y);
            a10 += fabsf(q1.z-k0v.z); a10 += fabsf(q1.w-k0v.w);
            a11 += fabsf(q1.x-k1v.x); a11 += fabsf(q1.y-k1v.y);
            a11 += fabsf(q1.z-k1v.z); a11 += fabsf(q1.w-k1v.w);
        }
        const float sK0 = g_sKp[0][b*SS + k0 + tx]      + g_sKp[1][b*SS + k0 + tx];
        const float sK1 = g_sKp[0][b*SS + k0 + tx + 16] + g_sKp[1][b*SS + k0 + tx + 16];

        float e00 = __expf(10.f - (sQ0 - sK0 + a00)*(10.f/256.f));
        float e01 = __expf(10.f - (sQ0 - sK1 + a01)*(10.f/256.f));
        float e10 = __expf(10.f - (sQ1 - sK0 + a10)*(10.f/256.f));
        float e11 = __expf(10.f - (sQ1 - sK1 + a11)*(10.f/256.f));
        if (causal) {
            int q0g = qt + ty, q1g = qt + ty + 16;
            int k0g = k0 + tx, k1g = k0 + tx + 16;
            if (k0g > q0g) e00 = 0.f;
            if (k1g > q0g) e01 = 0.f;
            if (k0g > q1g) e10 = 0.f;
            if (k1g > q1g) e11 = 0.f;
        }
        float l0 = e00 + e01, l1 = e10 + e11;
        #pragma unroll
        for (int o = 1; o < 16; o <<= 1) {
            l0 += __shfl_xor_sync(0xffffffffu, l0, o);
            l1 += __shfl_xor_sync(0xffffffffu, l1, o);
        }
        if (tx == 0) { rs0 += l0; rs1 += l1; }

        ss[ty*36 + tx]           = (e00 == 0.f) ? 0.f : e00 - 1.f;
        ss[ty*36 + tx + 16]      = (e01 == 0.f) ? 0.f : e01 - 1.f;
        ss[(ty+16)*36 + tx]      = (e10 == 0.f) ? 0.f : e10 - 1.f;
        ss[(ty+16)*36 + tx + 16] = (e11 == 0.f) ? 0.f : e11 - 1.f;

        asm volatile("cp.async.wait_group 0;\n" ::: "memory");
        __syncthreads();

        // --- PV accumulate (V from smem) ---
        #pragma unroll 2
        for (int kq = 0; kq < 8; kq++) {
            float4 p0 = *(const float4*)(ss + (ty2    )*36 + kq*4);
            float4 p1 = *(const float4*)(ss + (ty2+ 8)*36 + kq*4);
            float4 p2 = *(const float4*)(ss + (ty2+16)*36 + kq*4);
            float4 p3 = *(const float4*)(ss + (ty2+24)*36 + kq*4);
            #pragma unroll
            for (int c = 0; c < 4; c++) {
                float4 v = *(const float4*)(vs + (kq*4 + c)*132 + tx2*4);
                float pf0 = (&p0.x)[c], pf1 = (&p1.x)[c];
                float pf2 = (&p2.x)[c], pf3 = (&p3.x)[c];
                oacc[0].x += pf0*v.x; oacc[0].y += pf0*v.y; oacc[0].z += pf0*v.z; oacc[0].w += pf0*v.w;
                oacc[1].x += pf1*v.x; oacc[1].y += pf1*v.y; oacc[1].z += pf1*v.z; oacc[1].w += pf1*v.w;
                oacc[2].x += pf2*v.x; oacc[2].y += pf2*v.y; oacc[2].z += pf2*v.z; oacc[2].w += pf2*v.w;
                oacc[3].x += pf3*v.x; oacc[3].y += pf3*v.y; oacc[3].z += pf3*v.z; oacc[3].w += pf3*v.w;
            }
        }
    }

    float* dst = g_part[kc] + ((b << 10) + qt)*DD;
    #pragma unroll
    for (int i = 0; i < 4; i++)
        *(float4*)(dst + (ty2 + 8*i)*DD + tx2*4) = oacc[i];
    if (tx == 0) {
        g_rsum[kc][(b << 10) + qt + ty]      = rs0;
        g_rsum[kc][(b << 10) + qt + ty + 16] = rs1;
    }
}

// ---------------------------------------------------------------------------
// Reduce: out = (sum of active chunk partials + Vtot) * rinv.
// ---------------------------------------------------------------------------
__global__ __launch_bounds__(128) void out_reduce_kernel(float* __restrict__ out,
                                                          const int* __restrict__ maskflag)
{
    const int causal = (maskflag[0] != 0);
    int idx4 = blockIdx.x * 128 + threadIdx.x;
    int base = idx4 * 4;
    int row  = base >> 7;              // b*SS + q  (shared by all 32 lanes)
    int q    = row & (SS-1);
    int b    = row >> 10;
    int doff = base & 127;
    int lane = threadIdx.x & 31;

    int nc = causal ? ((q >> 6) + 1) : NCHUNK;

    float rp = (lane < nc) ? g_rsum[lane][row] : 0.f;
    #pragma unroll
    for (int o = 16; o > 0; o >>= 1) rp += __shfl_xor_sync(0xffffffffu, rp, o);
    float denom = rp + (causal ? (float)(SS - 1 - q) : 0.f);
    float rv = 1.f / denom;

    float4 s = *(const float4*)(g_vtot + (b << 7) + doff);
    #pragma unroll 4
    for (int j = 0; j < nc; j++) {
        float4 p = *(const float4*)(&g_part[j][base]);
        s.x += p.x; s.y += p.y; s.z += p.z; s.w += p.w;
    }
    s.x *= rv; s.y *= rv; s.z *= rv; s.w *= rv;
    *(float4*)(out + base) = s;
}

// ---------------------------------------------------------------------------
extern "C" void kernel_launch(void* const* d_in, const int* in_sizes, int n_in,
                              void* d_out, int out_size)
{
    const float* x  = (const float*)d_in[0];
    const float* Wq = (const float*)d_in[1];
    const float* bq = (const float*)d_in[2];
    const float* Wk = (const float*)d_in[3];
    const float* bk = (const float*)d_in[4];
    const float* Wv = (const float*)d_in[5];
    const float* bv = (const float*)d_in[6];
    const int*  msk = (const int*)d_in[7];
    float* out = (float*)d_out;

    cudaFuncSetAttribute(qkv_kernel,
                         cudaFuncAttributeMaxDynamicSharedMemorySize,
                         QKV_SMEM_BYTES);
    cudaFuncSetAttribute(fused_kernel,
                         cudaFuncAttributeMaxDynamicSharedMemorySize,
                         FUSED_SMEM_BYTES);

    qkv_kernel    <<<dim3(BB*SS/32, 2, 3), 256, QKV_SMEM_BYTES>>>(x, Wq, bq, Wk, bk, Wv, bv);
    fused_kernel  <<<dim3(513, BB), 256, FUSED_SMEM_BYTES>>>(msk);
    out_reduce_kernel<<<BB*SS*DD/512, 128>>>(out, msk);
}

// round 17
// speedup vs baseline: 1.3358x; 1.1809x over previous
#include <cuda_runtime.h>
#include <cuda_fp16.h>
#include <mma.h>

using namespace nvcuda;

#define BB 2
#define SS 1024
#define DD 128
#define NCHUNK 16          // k chunks of 64

// Scratch (device globals; allocation-free per harness rules)
__device__ float g_Q[BB*SS*DD];
__device__ float g_K[BB*SS*DD];
__device__ float g_V[BB*SS*DD];
__device__ float g_sQ[BB*SS];                 // row sums of Q
__device__ float g_sK[BB*SS];                 // row sums of K
__device__ float g_part[NCHUNK][BB*SS*DD];    // split-K partials ((P-1) weighted)
__device__ float g_rsum[NCHUNK][BB*SS];       // split-K partial row sums of exp
__device__ float g_vseg32[BB*32*DD];          // per-32-row segment sums of V (from qkv)
__device__ float g_vtot[BB*DD];               // total V row-sum per batch (from fused tail)

// ---------------------------------------------------------------------------
// K1: Q/K/V projection via WMMA (fp16 inputs, fp32 accumulate).
// Block = 32 rows x 128 e, one mat.  grid (64, 3), block 256 (8 warps).
// Warp w owns e-tile w (16 e) x 2 row-tiles; 8 k-steps of 16.
// smem: xh[32][136]h + wh[128][136]h = 43.5KB; cs[32][132]f overlaid after.
// ---------------------------------------------------------------------------
#define QKV_SMEM_BYTES (32*136*2 + 128*136*2)    // 43520

__global__ __launch_bounds__(256) void qkv_kernel(
    const float* __restrict__ x,
    const float* __restrict__ Wq, const float* __restrict__ bq,
    const float* __restrict__ Wk, const float* __restrict__ bk,
    const float* __restrict__ Wv, const float* __restrict__ bv)
{
    extern __shared__ char qsm[];
    __half* xh = (__half*)qsm;                   // [32][136]
    __half* wh = (__half*)(qsm + 32*136*2);      // [128][136]
    float*  cs = (float*)qsm;                    // [32][132] (after mma reads done)
    float*  vsum = (float*)(qsm + 24576);        // [16][132] (V epilogue scratch)

    const int t    = threadIdx.x;
    const int warp = t >> 5;
    const int mat  = blockIdx.y;
    const int rowbase = blockIdx.x * 32;

    const float* W    = (mat == 0) ? Wq : (mat == 1) ? Wk : Wv;
    const float* bias = (mat == 0) ? bq : (mat == 1) ? bk : bv;

    // convert x tile [32][128] -> fp16 (float4 loads, half2 stores)
    #pragma unroll
    for (int i = 0; i < 4; i++) {
        int lin = t + i*256;
        int r = lin >> 5, c = (lin & 31) * 4;
        float4 v = *(const float4*)(x + (rowbase + r)*DD + c);
        *(__half2*)(xh + r*136 + c)     = __floats2half2_rn(v.x, v.y);
        *(__half2*)(xh + r*136 + c + 2) = __floats2half2_rn(v.z, v.w);
    }
    // convert W [128][128] -> fp16
    #pragma unroll
    for (int i = 0; i < 16; i++) {
        int lin = t + i*256;
        int e = lin >> 5, c = (lin & 31) * 4;
        float4 v = *(const float4*)(W + e*DD + c);
        *(__half2*)(wh + e*136 + c)     = __floats2half2_rn(v.x, v.y);
        *(__half2*)(wh + e*136 + c + 2) = __floats2half2_rn(v.z, v.w);
    }
    __syncthreads();

    wmma::fragment<wmma::accumulator, 16, 16, 16, float> c0, c1;
    wmma::fill_fragment(c0, 0.f);
    wmma::fill_fragment(c1, 0.f);
    #pragma unroll
    for (int k = 0; k < 8; k++) {
        wmma::fragment<wmma::matrix_a, 16, 16, 16, __half, wmma::row_major> a0, a1;
        wmma::fragment<wmma::matrix_b, 16, 16, 16, __half, wmma::col_major> b;
        wmma::load_matrix_sync(a0, xh + k*16, 136);
        wmma::load_matrix_sync(a1, xh + 16*136 + k*16, 136);
        wmma::load_matrix_sync(b, wh + warp*16*136 + k*16, 136);
        wmma::mma_sync(c0, a0, b, c0);
        wmma::mma_sync(c1, a1, b, c1);
    }
    __syncthreads();                             // xh/wh reads complete
    wmma::store_matrix_sync(cs + warp*16, c0, 132, wmma::mem_row_major);
    wmma::store_matrix_sync(cs + 16*132 + warp*16, c1, 132, wmma::mem_row_major);
    __syncthreads();

    // epilogue: bias + activation + stores + row sums / V column sums
    const int tx = t & 15;                       // e = tx + 16*j
    const int ty = t >> 4;                       // rows ty, ty+16
    float* out = (mat == 0) ? g_Q : (mat == 1) ? g_K : g_V;
    float rsum[2] = {0.f, 0.f};
    float pairsum[8];
    #pragma unroll
    for (int j = 0; j < 8; j++) pairsum[j] = 0.f;

    #pragma unroll
    for (int i = 0; i < 2; i++) {
        int r = rowbase + ty + 16*i;
        #pragma unroll
        for (int j = 0; j < 8; j++) {
            int e = tx + 16*j;
            float v = cs[(ty + 16*i)*132 + e] + bias[e];
            if (mat < 2) v = 1.f / (1.f + __expf(-v));
            rsum[i] += v;
            pairsum[j] += v;
            out[r*DD + e] = v;
        }
    }
    if (mat < 2) {
        #pragma unroll
        for (int o = 1; o < 16; o <<= 1) {
            rsum[0] += __shfl_xor_sync(0xffffffffu, rsum[0], o);
            rsum[1] += __shfl_xor_sync(0xffffffffu, rsum[1], o);
        }
        if (tx == 0) {
            float* dst = (mat == 0) ? g_sQ : g_sK;
            dst[rowbase + ty]      = rsum[0];
            dst[rowbase + ty + 16] = rsum[1];
        }
    } else {
        __syncthreads();                         // cs reads complete
        #pragma unroll
        for (int j = 0; j < 8; j++)
            vsum[ty*132 + tx + 16*j] = pairsum[j];
        __syncthreads();
        if (t < 128) {
            float ssum = 0.f;
            #pragma unroll
            for (int r = 0; r < 16; r++) ssum += vsum[r*132 + t];
            g_vseg32[blockIdx.x * DD + t] = ssum;
        }
    }
}

// ---------------------------------------------------------------------------
// Triangular chunk base: B(qi) = qi + floor((qi-1)^2/4), B(0) = 0.
// ---------------------------------------------------------------------------
__device__ __forceinline__ int tri_base(int qi)
{
    return (qi == 0) ? 0 : qi + ((qi - 1)*(qi - 1)) / 4;
}

// ---------------------------------------------------------------------------
// Fused flash-style kernel (R14-core; single g_sQ/g_sK reads).  Tail block
// (x==512, y==0) computes g_vtot.  grid (513, B), block 256.
// ---------------------------------------------------------------------------
#define QS_OFF 0
#define KS_OFF (32*132)
#define VS_OFF (2*32*132)
#define SS_OFF (3*32*132)
#define FUSED_SMEM_BYTES ((3*32*132 + 32*36) * 4)

__global__ __launch_bounds__(256) void fused_kernel(const int* __restrict__ maskflag)
{
    const int causal = (maskflag[0] != 0);
    const int n = blockIdx.x;
    const int b = blockIdx.y;

    if (n == 512) {                       // vtot tail block
        if (b == 0) {
            int bb = threadIdx.x >> 7, d = threadIdx.x & 127;
            float a = 0.f;
            #pragma unroll 8
            for (int s2 = 0; s2 < 32; s2++)
                a += g_vseg32[(bb*32 + s2)*DD + d];
            g_vtot[bb*DD + d] = a;
        }
        return;
    }

    int qi, kc;
    if (causal) {
        if (n >= 272) return;
        qi = (int)(2.f * sqrtf((float)n + 1.f)) - 2;
        if (qi < 0) qi = 0;
        if (qi > 31) qi = 31;
        while (qi < 31 && tri_base(qi + 1) <= n) qi++;
        while (qi > 0  && tri_base(qi) > n)      qi--;
        kc = n - tri_base(qi);
    } else {
        qi = n >> 4;
        kc = n & 15;
    }
    const int qt = qi * 32;

    extern __shared__ float smem[];
    float* qs = smem + QS_OFF;
    float* ks = smem + KS_OFF;
    float* vs = smem + VS_OFF;
    float* ss = smem + SS_OFF;

    const int t  = threadIdx.x;
    const int tx = t & 15;         // score: k = k0 + tx, +16
    const int ty = t >> 4;         // score: q = qt + ty, +16
    const int tx2 = t & 31;        // pv: d = tx2*4
    const int ty2 = t >> 5;        // pv: q = ty2 + 8i

    const float* Qb = g_Q + b*SS*DD;
    const float* Kb = g_K + b*SS*DD;
    const float* Vb = g_V + b*SS*DD;

    #pragma unroll
    for (int i = 0; i < 4; i++) {
        int lin = t + i*256;
        int r = lin >> 5, c = (lin & 31) * 4;
        *(float4*)(qs + r*132 + c) = *(const float4*)(Qb + (qt + r)*DD + c);
    }
    const float sQ0 = g_sQ[b*SS + qt + ty];
    const float sQ1 = g_sQ[b*SS + qt + ty + 16];

    float4 oacc[4];
    #pragma unroll
    for (int i = 0; i < 4; i++) oacc[i] = make_float4(0.f,0.f,0.f,0.f);
    float rs0 = 0.f, rs1 = 0.f;

    #pragma unroll
    for (int s = 0; s < 2; s++) {
        const int k0 = kc*64 + s*32;

        __syncthreads();
        // async V tile prefetch (lands before PV; overlapped with score)
        #pragma unroll
        for (int i = 0; i < 4; i++) {
            int lin = t + i*256;
            int r = lin >> 5, c = (lin & 31) * 4;
            unsigned dst = (unsigned)__cvta_generic_to_shared(vs + r*132 + c);
            const float* src = Vb + (k0 + r)*DD + c;
            asm volatile("cp.async.cg.shared.global [%0], [%1], 16;\n"
                         :: "r"(dst), "l"(src) : "memory");
        }
        asm volatile("cp.async.commit_group;\n" ::: "memory");
        // K tile (regular ld/st; covered by the next barrier)
        #pragma unroll
        for (int i = 0; i < 4; i++) {
            int lin = t + i*256;
            int r = lin >> 5, c = (lin & 31) * 4;
            *(float4*)(ks + r*132 + c) = *(const float4*)(Kb + (k0 + r)*DD + c);
        }
        __syncthreads();

        // --- score: A = sum_d |q - k| ---
        float a00 = 0.f, a01 = 0.f, a10 = 0.f, a11 = 0.f;
        #pragma unroll 8
        for (int dq = 0; dq < 32; dq++) {
            float4 q0 = *(const float4*)(qs + ty*132 + dq*4);
            float4 q1 = *(const float4*)(qs + (ty+16)*132 + dq*4);
            float4 k0v = *(const float4*)(ks + tx*132 + dq*4);
            float4 k1v = *(const float4*)(ks + (tx+16)*132 + dq*4);
            a00 += fabsf(q0.x-k0v.x); a00 += fabsf(q0.y-k0v.y);
            a00 += fabsf(q0.z-k0v.z); a00 += fabsf(q0.w-k0v.w);
            a01 += fabsf(q0.x-k1v.x); a01 += fabsf(q0.y-k1v.y);
            a01 += fabsf(q0.z-k1v.z); a01 += fabsf(q0.w-k1v.w);
            a10 += fabsf(q1.x-k0v.x); a10 += fabsf(q1.y-k0v.y);
            a10 += fabsf(q1.z-k0v.z); a10 += fabsf(q1.w-k0v.w);
            a11 += fabsf(q1.x-k1v.x); a11 += fabsf(q1.y-k1v.y);
            a11 += fabsf(q1.z-k1v.z); a11 += fabsf(q1.w-k1v.w);
        }
        const float sK0 = g_sK[b*SS + k0 + tx];
        const float sK1 = g_sK[b*SS + k0 + tx + 16];

        float e00 = __expf(10.f - (sQ0 - sK0 + a00)*(10.f/256.f));
        float e01 = __expf(10.f - (sQ0 - sK1 + a01)*(10.f/256.f));
        float e10 = __expf(10.f - (sQ1 - sK0 + a10)*(10.f/256.f));
        float e11 = __expf(10.f - (sQ1 - sK1 + a11)*(10.f/256.f));
        if (causal) {
            int q0g = qt + ty, q1g = qt + ty + 16;
            int k0g = k0 + tx, k1g = k0 + tx + 16;
            if (k0g > q0g) e00 = 0.f;
            if (k1g > q0g) e01 = 0.f;
            if (k0g > q1g) e10 = 0.f;
            if (k1g > q1g) e11 = 0.f;
        }
        float l0 = e00 + e01, l1 = e10 + e11;
        #pragma unroll
        for (int o = 1; o < 16; o <<= 1) {
            l0 += __shfl_xor_sync(0xffffffffu, l0, o);
            l1 += __shfl_xor_sync(0xffffffffu, l1, o);
        }
        if (tx == 0) { rs0 += l0; rs1 += l1; }

        ss[ty*36 + tx]           = (e00 == 0.f) ? 0.f : e00 - 1.f;
        ss[ty*36 + tx + 16]      = (e01 == 0.f) ? 0.f : e01 - 1.f;
        ss[(ty+16)*36 + tx]      = (e10 == 0.f) ? 0.f : e10 - 1.f;
        ss[(ty+16)*36 + tx + 16] = (e11 == 0.f) ? 0.f : e11 - 1.f;

        asm volatile("cp.async.wait_group 0;\n" ::: "memory");
        __syncthreads();

        // --- PV accumulate (V from smem) ---
        #pragma unroll 2
        for (int kq = 0; kq < 8; kq++) {
            float4 p0 = *(const float4*)(ss + (ty2    )*36 + kq*4);
            float4 p1 = *(const float4*)(ss + (ty2+ 8)*36 + kq*4);
            float4 p2 = *(const float4*)(ss + (ty2+16)*36 + kq*4);
            float4 p3 = *(const float4*)(ss + (ty2+24)*36 + kq*4);
            #pragma unroll
            for (int c = 0; c < 4; c++) {
                float4 v = *(const float4*)(vs + (kq*4 + c)*132 + tx2*4);
                float pf0 = (&p0.x)[c], pf1 = (&p1.x)[c];
                float pf2 = (&p2.x)[c], pf3 = (&p3.x)[c];
                oacc[0].x += pf0*v.x; oacc[0].y += pf0*v.y; oacc[0].z += pf0*v.z; oacc[0].w += pf0*v.w;
                oacc[1].x += pf1*v.x; oacc[1].y += pf1*v.y; oacc[1].z += pf1*v.z; oacc[1].w += pf1*v.w;
                oacc[2].x += pf2*v.x; oacc[2].y += pf2*v.y; oacc[2].z += pf2*v.z; oacc[2].w += pf2*v.w;
                oacc[3].x += pf3*v.x; oacc[3].y += pf3*v.y; oacc[3].z += pf3*v.z; oacc[3].w += pf3*v.w;
            }
        }
    }

    float* dst = g_part[kc] + ((b << 10) + qt)*DD;
    #pragma unroll
    for (int i = 0; i < 4; i++)
        *(float4*)(dst + (ty2 + 8*i)*DD + tx2*4) = oacc[i];
    if (tx == 0) {
        g_rsum[kc][(b << 10) + qt + ty]      = rs0;
        g_rsum[kc][(b << 10) + qt + ty + 16] = rs1;
    }
}

// ---------------------------------------------------------------------------
// Reduce: out = (sum of active chunk partials + Vtot) * rinv.
// ---------------------------------------------------------------------------
__global__ __launch_bounds__(128) void out_reduce_kernel(float* __restrict__ out,
                                                          const int* __restrict__ maskflag)
{
    const int causal = (maskflag[0] != 0);
    int idx4 = blockIdx.x * 128 + threadIdx.x;
    int base = idx4 * 4;
    int row  = base >> 7;              // b*SS + q  (shared by all 32 lanes)
    int q    = row & (SS-1);
    int b    = row >> 10;
    int doff = base & 127;
    int lane = threadIdx.x & 31;

    int nc = causal ? ((q >> 6) + 1) : NCHUNK;

    float rp = (lane < nc) ? g_rsum[lane][row] : 0.f;
    #pragma unroll
    for (int o = 16; o > 0; o >>= 1) rp += __shfl_xor_sync(0xffffffffu, rp, o);
    float denom = rp + (causal ? (float)(SS - 1 - q) : 0.f);
    float rv = 1.f / denom;

    float4 s = *(const float4*)(g_vtot + (b << 7) + doff);
    #pragma unroll 4
    for (int j = 0; j < nc; j++) {
        float4 p = *(const float4*)(&g_part[j][base]);
        s.x += p.x; s.y += p.y; s.z += p.z; s.w += p.w;
    }
    s.x *= rv; s.y *= rv; s.z *= rv; s.w *= rv;
    *(float4*)(out + base) = s;
}

// ---------------------------------------------------------------------------
extern "C" void kernel_launch(void* const* d_in, const int* in_sizes, int n_in,
                              void* d_out, int out_size)
{
    const float* x  = (const float*)d_in[0];
    const float* Wq = (const float*)d_in[1];
    const float* bq = (const float*)d_in[2];
    const float* Wk = (const float*)d_in[3];
    const float* bk = (const float*)d_in[4];
    const float* Wv = (const float*)d_in[5];
    const float* bv = (const float*)d_in[6];
    const int*  msk = (const int*)d_in[7];
    float* out = (float*)d_out;

    cudaFuncSetAttribute(qkv_kernel,
                         cudaFuncAttributeMaxDynamicSharedMemorySize,
                         QKV_SMEM_BYTES);
    cudaFuncSetAttribute(fused_kernel,
                         cudaFuncAttributeMaxDynamicSharedMemorySize,
                         FUSED_SMEM_BYTES);

    qkv_kernel    <<<dim3(BB*SS/32, 3), 256, QKV_SMEM_BYTES>>>(x, Wq, bq, Wk, bk, Wv, bv);
    fused_kernel  <<<dim3(513, BB), 256, FUSED_SMEM_BYTES>>>(msk);
    out_reduce_kernel<<<BB*SS*DD/512, 128>>>(out, msk);
}